// round 12
// baseline (speedup 1.0000x reference)
#include <cuda_runtime.h>
#include <cuda_bf16.h>
#include <cstdint>

#define IH 256
#define IW 256
#define HWX 65536
#define WTOT 617472

__device__ float g_bufA[2 * 64 * HWX];
__device__ float g_bufB[2 * 64 * HWX];
__device__ float g_raw[2 * 216 * HWX];
__device__ float g_col[2 * 576 * HWX];
__device__ float g_cat[128 * HWX];
__device__ __nv_bfloat16 g_wbf[2 * WTOT];   // hi plane, then lo plane

// ---------------- helpers ----------------
__device__ __forceinline__ uint32_t smem_u32(const void* p) {
    return (uint32_t)__cvta_generic_to_shared(p);
}
__device__ __forceinline__ void ldsm4(uint32_t& r0, uint32_t& r1, uint32_t& r2, uint32_t& r3, uint32_t a) {
    asm volatile("ldmatrix.sync.aligned.m8n8.x4.shared.b16 {%0,%1,%2,%3}, [%4];"
                 : "=r"(r0), "=r"(r1), "=r"(r2), "=r"(r3) : "r"(a));
}
__device__ __forceinline__ void mma16816(float* d, const uint32_t* a, uint32_t b0, uint32_t b1) {
    asm volatile("mma.sync.aligned.m16n8k16.row.col.f32.bf16.bf16.f32 "
                 "{%0,%1,%2,%3}, {%4,%5,%6,%7}, {%8,%9}, {%0,%1,%2,%3};"
                 : "+f"(d[0]), "+f"(d[1]), "+f"(d[2]), "+f"(d[3])
                 : "r"(a[0]), "r"(a[1]), "r"(a[2]), "r"(a[3]), "r"(b0), "r"(b1));
}
__device__ __forceinline__ void cp16(uint32_t daddr, const void* src, int src_sz) {
    asm volatile("cp.async.cg.shared.global [%0], [%1], 16, %2;"
                 :: "r"(daddr), "l"(src), "r"(src_sz));
}
__device__ __forceinline__ void cp_commit() { asm volatile("cp.async.commit_group;"); }
__device__ __forceinline__ void cp_wait1() { asm volatile("cp.async.wait_group 1;"); }
__device__ __forceinline__ void cp_wait0() { asm volatile("cp.async.wait_group 0;"); }

// ---------------- weight split: fp32 -> bf16 hi/lo planes ----------------
__global__ __launch_bounds__(256) void split_w_k(const float* __restrict__ w, int n, int dst,
                                                 __nv_bfloat16* __restrict__ wbf)
{
    int i = (blockIdx.x * 256 + threadIdx.x) * 4;
    if (i >= n) return;
    float4 v = *(const float4*)(w + i);
    __nv_bfloat16 h0 = __float2bfloat16(v.x), h1 = __float2bfloat16(v.y);
    __nv_bfloat16 h2 = __float2bfloat16(v.z), h3 = __float2bfloat16(v.w);
    uint2 hp, lp;
    hp.x = ((uint32_t)__bfloat16_as_ushort(h1) << 16) | __bfloat16_as_ushort(h0);
    hp.y = ((uint32_t)__bfloat16_as_ushort(h3) << 16) | __bfloat16_as_ushort(h2);
    __nv_bfloat16 g0 = __float2bfloat16(v.x - __bfloat162float(h0));
    __nv_bfloat16 g1 = __float2bfloat16(v.y - __bfloat162float(h1));
    __nv_bfloat16 g2 = __float2bfloat16(v.z - __bfloat162float(h2));
    __nv_bfloat16 g3 = __float2bfloat16(v.w - __bfloat162float(h3));
    lp.x = ((uint32_t)__bfloat16_as_ushort(g1) << 16) | __bfloat16_as_ushort(g0);
    lp.y = ((uint32_t)__bfloat16_as_ushort(g3) << 16) | __bfloat16_as_ushort(g2);
    *(uint2*)(wbf + dst + i) = hp;
    *(uint2*)(wbf + WTOT + dst + i) = lp;
}

// ---------------- HMMA implicit-GEMM 3x3 conv ----------------
// D[128 oc][128 px] = A[oc][kg] x B[px][kg]^T,  kg = cin*9+tap, chunks of 64.
// 8 warps: warp = (mwarp 0..3) x (nwarp 0..1); warp tile 32 oc x 64 px.
// A/B smem rows stride 72 bf16 (144 B) -> conflict-free ldmatrix.
// grid: (512 = 256 rows x 2 col-halves, branches*mtiles), 256 threads.
#define SMA_OFF(t) ((uint32_t)((t) * 18432))
#define SMB_OFF(t) ((uint32_t)(36864 + (t) * 18432))
#define SMS_OFF 73728u
#define CONV_SMEM (73728 + 33792)

template <int KTOT, bool LRELU>
__global__ __launch_bounds__(256) void conv_mma_k(
    const float* __restrict__ x0, const float* __restrict__ x1,
    const __nv_bfloat16* __restrict__ wbf, int woff0, int woff1,
    const float* __restrict__ bias0, const float* __restrict__ bias1,
    float* __restrict__ y0, float* __restrict__ y1,
    int cout, int mtiles)
{
    extern __shared__ __align__(16) char sm[];
    const uint32_t sb = smem_u32(sm);
    float* stage = (float*)(sm + SMS_OFF);   // [px 128][kg 64], stride 66

    const int tid = threadIdx.x;
    const int wid = tid >> 5, lane = tid & 31;
    const int mwarp = wid >> 1, nwarp = wid & 1;
    const int h = blockIdx.x >> 1;
    const int w0p = (blockIdx.x & 1) * 128;
    const int branch = blockIdx.y / mtiles;
    const int mtile = blockIdx.y - branch * mtiles;
    const float* x = branch ? x1 : x0;
    const float* bias = branch ? bias1 : bias0;
    float* y = branch ? y1 : y0;
    const int woff = branch ? woff1 : woff0;
    const int ocb = mtile * 128;
    const int crows = min(128, cout - ocb);

    constexpr int NCH = KTOT / 64;

    const int arow = tid >> 1, ahalf = tid & 1;
    const bool vrow = arow < crows;

    float acc[2][8][4];
#pragma unroll
    for (int mi = 0; mi < 2; ++mi)
#pragma unroll
        for (int ni = 0; ni < 8; ++ni)
#pragma unroll
            for (int q = 0; q < 4; ++q) acc[mi][ni][q] = 0.f;

    // per-warp ldmatrix base offsets (lane-dependent row/k-half)
    const uint32_t lrow = lane & 15;
    const uint32_t lkoff = (lane >> 4) * 16;  // bytes
    const uint32_t a_base0 = sb + (uint32_t)(mwarp * 32 + lrow) * 144 + lkoff;
    const uint32_t b_base0 = sb + (uint32_t)(nwarp * 64 + lrow) * 144 + lkoff;

#pragma unroll 1
    for (int c = 0; c < NCH; ++c) {
        // ---- A: copy pre-split bf16 weights (128 oc x 64 kg, stride 72) ----
        {
            const uint4 z = make_uint4(0, 0, 0, 0);
            const uint4* sh = (const uint4*)(wbf + woff + (size_t)(ocb + arow) * KTOT + c * 64 + ahalf * 32);
            const uint4* sl = (const uint4*)((const __nv_bfloat16*)sh + WTOT);
            char* da0 = sm + SMA_OFF(0) + arow * 144 + ahalf * 64;
            char* da1 = sm + SMA_OFF(1) + arow * 144 + ahalf * 64;
#pragma unroll
            for (int j = 0; j < 4; ++j) {
                *(uint4*)(da0 + j * 16) = vrow ? __ldg(sh + j) : z;
                *(uint4*)(da1 + j * 16) = vrow ? __ldg(sl + j) : z;
            }
        }

        // ---- phase 1: coalesced LDG -> fp32 staging [px][kg] ----
#pragma unroll
        for (int j = 0; j < 8; ++j) {
            int kg = wid * 8 + j;
            int kga = c * 64 + kg;
            int cin = kga / 9, tap = kga - cin * 9;
            int ky = tap / 3, kx = tap - 3 * ky;
            int yy = h + ky - 1;
            bool rv = (unsigned)yy < IH;
            const float* src = x + (size_t)cin * HWX + yy * IW + (w0p - 1 + kx);
            int bad = (w0p == 0) ? (kx == 0 ? 0 : -1) : (kx == 2 ? 127 : -1);
#pragma unroll
            for (int i = 0; i < 4; ++i) {
                int px = lane + 32 * i;
                float v = (rv && px != bad) ? __ldg(src + px) : 0.f;
                stage[px * 66 + kg] = v;
            }
        }
        __syncthreads();

        // ---- phase 2: transpose + bf16 hi/lo split -> B smem (stride 72) ----
        {
            char* bh = sm + SMB_OFF(0);
            char* bl = sm + SMB_OFF(1);
#pragma unroll
            for (int it = 0; it < 16; ++it) {
                int p = wid + 8 * it;
                float2 v = *(const float2*)(stage + p * 66 + 2 * lane);
                __nv_bfloat16 h0 = __float2bfloat16(v.x);
                __nv_bfloat16 h1 = __float2bfloat16(v.y);
                uint32_t hp = ((uint32_t)__bfloat16_as_ushort(h1) << 16) | __bfloat16_as_ushort(h0);
                __nv_bfloat16 g0 = __float2bfloat16(v.x - __bfloat162float(h0));
                __nv_bfloat16 g1 = __float2bfloat16(v.y - __bfloat162float(h1));
                uint32_t lp = ((uint32_t)__bfloat16_as_ushort(g1) << 16) | __bfloat16_as_ushort(g0);
                *(uint32_t*)(bh + p * 144 + lane * 4) = hp;
                *(uint32_t*)(bl + p * 144 + lane * 4) = lp;
            }
        }
        __syncthreads();

        // ---- compute: 4 k-steps of 16, 3 products (AhBh + AhBl + AlBh) ----
#pragma unroll
        for (int ks = 0; ks < 4; ++ks) {
            uint32_t ah[2][4], al[2][4];
#pragma unroll
            for (int mi = 0; mi < 2; ++mi) {
                ldsm4(ah[mi][0], ah[mi][1], ah[mi][2], ah[mi][3],
                      a_base0 + SMA_OFF(0) + mi * 16 * 144 + ks * 32);
                ldsm4(al[mi][0], al[mi][1], al[mi][2], al[mi][3],
                      a_base0 + SMA_OFF(1) + mi * 16 * 144 + ks * 32);
            }
#pragma unroll
            for (int ni2 = 0; ni2 < 4; ++ni2) {
                uint32_t bh0, bh1, bh2, bh3, bl0, bl1, bl2, bl3;
                ldsm4(bh0, bh1, bh2, bh3, b_base0 + SMB_OFF(0) + ni2 * 16 * 144 + ks * 32);
                ldsm4(bl0, bl1, bl2, bl3, b_base0 + SMB_OFF(1) + ni2 * 16 * 144 + ks * 32);
#pragma unroll
                for (int mi = 0; mi < 2; ++mi) {
                    float* d0 = acc[mi][2 * ni2];
                    float* d1 = acc[mi][2 * ni2 + 1];
                    mma16816(d0, ah[mi], bh0, bh2);
                    mma16816(d0, ah[mi], bl0, bl2);
                    mma16816(d0, al[mi], bh0, bh2);
                    mma16816(d1, ah[mi], bh1, bh3);
                    mma16816(d1, ah[mi], bl1, bl3);
                    mma16816(d1, al[mi], bh1, bh3);
                }
            }
        }
        __syncthreads();
    }

    // ---- epilogue: fragments -> global, bias + lrelu ----
    const int colb = w0p + nwarp * 64 + (lane & 3) * 2;
#pragma unroll
    for (int mi = 0; mi < 2; ++mi) {
        int r0 = mwarp * 32 + mi * 16 + (lane >> 2);
        int r1 = r0 + 8;
#pragma unroll
        for (int half = 0; half < 2; ++half) {
            int r = half ? r1 : r0;
            if (r < crows) {
                float bv = __ldg(bias + ocb + r);
                float* dst = y + (size_t)(ocb + r) * HWX + h * IW;
#pragma unroll
                for (int ni = 0; ni < 8; ++ni) {
                    float v0 = acc[mi][ni][half * 2 + 0] + bv;
                    float v1 = acc[mi][ni][half * 2 + 1] + bv;
                    if (LRELU) {
                        v0 = v0 >= 0.f ? v0 : 0.1f * v0;
                        v1 = v1 >= 0.f ? v1 : 0.1f * v1;
                    }
                    *(float2*)(dst + colb + ni * 8) = make_float2(v0, v1);
                }
            }
        }
    }
}

// ---------------- deformable sampling -> col ----------------
__global__ __launch_bounds__(256) void sample_k(
    const float* __restrict__ f0, const float* __restrict__ f1,
    const float* __restrict__ rawb,
    const float* __restrict__ fl0, const float* __restrict__ fl1,
    float* __restrict__ colb)
{
    const int br = blockIdx.y;
    const float* feat = br ? f1 : f0;
    const float* raw = rawb + (size_t)br * 216 * HWX;
    const float* flow = br ? fl1 : fl0;
    float* col = colb + (size_t)br * 576 * HWX;

    const int txl = threadIdx.x;
    const int g = threadIdx.y;
    const int p = blockIdx.x * 32 + txl;
    const int h = p >> 8;
    const int w = p & 255;

    const float fy = flow[HWX + p];
    const float fx = flow[p];

#pragma unroll 1
    for (int k = 0; k < 9; ++k) {
        const int kyv = k / 3 - 1;
        const int kxv = k % 3 - 1;
        const int ch = g * 18 + k * 2;

        float ry = raw[(size_t)ch * HWX + p];
        float rx = raw[(size_t)(ch + 1) * HWX + p];
        float rm = raw[(size_t)(144 + g * 9 + k) * HWX + p];

        float ey = __expf(2.f * ry);
        float oy = 10.f * (1.f - 2.f / (ey + 1.f));
        float ex = __expf(2.f * rx);
        float ox = 10.f * (1.f - 2.f / (ex + 1.f));
        float m = 1.f / (1.f + __expf(-rm));

        float py = (float)h + (float)kyv + oy + fy;
        float px = (float)w + (float)kxv + ox + fx;
        float y0f = floorf(py), x0f = floorf(px);
        float ly = py - y0f, lx = px - x0f;
        int y0 = (int)y0f, x0 = (int)x0f;
        int y1 = y0 + 1, x1 = x0 + 1;

        bool vy0 = (y0 >= 0) && (y0 < IH);
        bool vy1 = (y1 >= 0) && (y1 < IH);
        bool vx0 = (x0 >= 0) && (x0 < IW);
        bool vx1 = (x1 >= 0) && (x1 < IW);

        float w00 = (vy0 && vx0) ? (1.f - ly) * (1.f - lx) * m : 0.f;
        float w01 = (vy0 && vx1) ? (1.f - ly) * lx * m : 0.f;
        float w10 = (vy1 && vx0) ? ly * (1.f - lx) * m : 0.f;
        float w11 = (vy1 && vx1) ? ly * lx * m : 0.f;

        int y0c = min(max(y0, 0), IH - 1), y1c = min(max(y1, 0), IH - 1);
        int x0c = min(max(x0, 0), IW - 1), x1c = min(max(x1, 0), IW - 1);
        int i00 = y0c * IW + x0c, i01 = y0c * IW + x1c;
        int i10 = y1c * IW + x0c, i11 = y1c * IW + x1c;

        const float* xb = feat + (size_t)g * 8 * HWX;
#pragma unroll
        for (int c = 0; c < 8; ++c) {
            const float* xc = xb + (size_t)c * HWX;
            float s = w00 * __ldg(xc + i00) + w01 * __ldg(xc + i01)
                    + w10 * __ldg(xc + i10) + w11 * __ldg(xc + i11);
            col[((size_t)((g * 8 + c) * 9 + k)) * HWX + p] = s;
        }
    }
}

// ---------------- GEMM: out[64][65536] = W[64][576] @ col + b ----------------
__global__ __launch_bounds__(256, 2) void gemm_col_k(
    const float* __restrict__ colb,
    const float* __restrict__ wg0, const float* __restrict__ wg1,
    const float* __restrict__ bi0, const float* __restrict__ bi1,
    float* __restrict__ outb)
{
    extern __shared__ float smem[];
    float* s_w = smem;
    float* s_c = smem + 576 * 8;

    const int tid = threadIdx.x;
    const int pb = blockIdx.x * 2048;
    const int ocb = blockIdx.y * 8;
    const int br = blockIdx.z;
    const float* col = colb + (size_t)br * 576 * HWX;
    const float* wgt = br ? wg1 : wg0;
    const float* bias = br ? bi1 : bi0;
    float* out = outb + (size_t)br * 64 * HWX;

    for (int idx = tid; idx < 576 * 8; idx += 256) {
        int i = idx >> 3;
        int oc = idx & 7;
        s_w[idx] = wgt[(ocb + oc) * 576 + i];
    }

    const uint32_t sc_base = smem_u32(s_c);
    auto stage_chunk = [&](int chunk, int buf) {
        int i0 = chunk * 4;
        uint32_t dbase = sc_base + (uint32_t)buf * (4 * 2048 * 4);
#pragma unroll
        for (int j = 0; j < 8; ++j) {
            int flat = tid + j * 256;
            int row = flat >> 9;
            int c4 = flat & 511;
            cp16(dbase + (uint32_t)(row * 2048 + c4 * 4) * 4,
                 col + (size_t)(i0 + row) * HWX + pb + c4 * 4, 16);
        }
    };

    float acc[8][8];
#pragma unroll
    for (int oc = 0; oc < 8; ++oc)
#pragma unroll
        for (int q = 0; q < 8; ++q) acc[oc][q] = 0.f;

    stage_chunk(0, 0);
    cp_commit();

#pragma unroll 1
    for (int c = 0; c < 144; ++c) {
        if (c + 1 < 144) {
            stage_chunk(c + 1, (c + 1) & 1);
            cp_commit();
            cp_wait1();
        } else {
            cp_wait0();
        }
        __syncthreads();

        const float* sbuf = s_c + (c & 1) * (4 * 2048);
#pragma unroll
        for (int kk = 0; kk < 4; ++kk) {
            float4 a = *reinterpret_cast<const float4*>(sbuf + kk * 2048 + tid * 4);
            float4 b = *reinterpret_cast<const float4*>(sbuf + kk * 2048 + 1024 + tid * 4);
            const float* wr = &s_w[(c * 4 + kk) * 8];
#pragma unroll
            for (int oc = 0; oc < 8; ++oc) {
                float wv = wr[oc];
                acc[oc][0] = fmaf(a.x, wv, acc[oc][0]);
                acc[oc][1] = fmaf(a.y, wv, acc[oc][1]);
                acc[oc][2] = fmaf(a.z, wv, acc[oc][2]);
                acc[oc][3] = fmaf(a.w, wv, acc[oc][3]);
                acc[oc][4] = fmaf(b.x, wv, acc[oc][4]);
                acc[oc][5] = fmaf(b.y, wv, acc[oc][5]);
                acc[oc][6] = fmaf(b.z, wv, acc[oc][6]);
                acc[oc][7] = fmaf(b.w, wv, acc[oc][7]);
            }
        }
        __syncthreads();
    }

#pragma unroll
    for (int oc = 0; oc < 8; ++oc) {
        float bv = bias[ocb + oc];
        float4 o1, o2;
        o1.x = acc[oc][0] + bv; o1.y = acc[oc][1] + bv;
        o1.z = acc[oc][2] + bv; o1.w = acc[oc][3] + bv;
        o2.x = acc[oc][4] + bv; o2.y = acc[oc][5] + bv;
        o2.z = acc[oc][6] + bv; o2.w = acc[oc][7] + bv;
        *reinterpret_cast<float4*>(&out[(size_t)(ocb + oc) * HWX + pb + tid * 4]) = o1;
        *reinterpret_cast<float4*>(&out[(size_t)(ocb + oc) * HWX + pb + 1024 + tid * 4]) = o2;
    }
}

// ---------------- host side ----------------
extern "C" void kernel_launch(void* const* d_in, const int* in_sizes, int n_in,
                              void* d_out, int out_size)
{
    (void)in_sizes; (void)n_in; (void)out_size;

    float *bufA, *bufB, *raw, *colp, *cat;
    __nv_bfloat16* wbf;
    cudaGetSymbolAddress((void**)&bufA, g_bufA);
    cudaGetSymbolAddress((void**)&bufB, g_bufB);
    cudaGetSymbolAddress((void**)&raw, g_raw);
    cudaGetSymbolAddress((void**)&colp, g_col);
    cudaGetSymbolAddress((void**)&cat, g_cat);
    cudaGetSymbolAddress((void**)&wbf, g_wbf);

    const float* feat0  = (const float*)d_in[0];
    const float* feat1  = (const float*)d_in[1];
    const float* extra0 = (const float*)d_in[2];
    const float* extra1 = (const float*)d_in[3];
    const float* flow0  = (const float*)d_in[4];
    const float* flow1  = (const float*)d_in[5];

    const size_t OFF64 = (size_t)64 * HWX;

    const float* Bb[2][4];
    for (int br = 0; br < 2; ++br)
        for (int j = 0; j < 4; ++j)
            Bb[br][j] = (const float*)d_in[6 + br * 8 + j * 2 + 1];
    const float* dw1 = (const float*)d_in[22];
    const float* db1 = (const float*)d_in[23];
    const float* dw2 = (const float*)d_in[24];
    const float* db2 = (const float*)d_in[25];
    const float* fb  = (const float*)d_in[27];

    const int SM_GEMM = (576 * 8 + 2 * 4 * 2048) * 4;
    cudaFuncSetAttribute(conv_mma_k<1152, true>,  cudaFuncAttributeMaxDynamicSharedMemorySize, CONV_SMEM);
    cudaFuncSetAttribute(conv_mma_k<576, true>,   cudaFuncAttributeMaxDynamicSharedMemorySize, CONV_SMEM);
    cudaFuncSetAttribute(conv_mma_k<576, false>,  cudaFuncAttributeMaxDynamicSharedMemorySize, CONV_SMEM);
    cudaFuncSetAttribute(conv_mma_k<1152, false>, cudaFuncAttributeMaxDynamicSharedMemorySize, CONV_SMEM);
    cudaFuncSetAttribute(gemm_col_k,              cudaFuncAttributeMaxDynamicSharedMemorySize, SM_GEMM);

    // weight split prologue: {input index, elems, dst offset}
    const int L[9][3] = {
        {6, 73728, 0},       {8, 36864, 73728},   {10, 36864, 110592}, {12, 124416, 147456},
        {14, 73728, 271872}, {16, 36864, 345600}, {18, 36864, 382464}, {20, 124416, 419328},
        {26, 73728, 543744}};
    for (int i = 0; i < 9; ++i)
        split_w_k<<<(L[i][1] / 4 + 255) / 256, 256>>>((const float*)d_in[L[i][0]], L[i][1], L[i][2], wbf);

    conv_mma_k<1152, true><<<dim3(512, 2), 256, CONV_SMEM>>>(
        extra0, extra1, wbf, 0, 271872, Bb[0][0], Bb[1][0], bufA, bufA + OFF64, 64, 1);
    conv_mma_k<576, true><<<dim3(512, 2), 256, CONV_SMEM>>>(
        bufA, bufA + OFF64, wbf, 73728, 345600, Bb[0][1], Bb[1][1], bufB, bufB + OFF64, 64, 1);
    conv_mma_k<576, true><<<dim3(512, 2), 256, CONV_SMEM>>>(
        bufB, bufB + OFF64, wbf, 110592, 382464, Bb[0][2], Bb[1][2], bufA, bufA + OFF64, 64, 1);
    conv_mma_k<576, false><<<dim3(512, 4), 256, CONV_SMEM>>>(
        bufA, bufA + OFF64, wbf, 147456, 419328, Bb[0][3], Bb[1][3],
        raw, raw + (size_t)216 * HWX, 216, 2);

    sample_k<<<dim3(2048, 2), dim3(32, 8)>>>(feat0, feat1, raw, flow0, flow1, colp);
    gemm_col_k<<<dim3(32, 8, 2), 256, SM_GEMM>>>(colp, dw1, dw2, db1, db2, cat);

    conv_mma_k<1152, false><<<dim3(512, 1), 256, CONV_SMEM>>>(
        cat, cat, wbf, 543744, 543744, fb, fb, (float*)d_out, (float*)d_out, 64, 1);
}

// round 14
// speedup vs baseline: 1.2501x; 1.2501x over previous
#include <cuda_runtime.h>
#include <cuda_bf16.h>
#include <cstdint>

#define IH 256
#define IW 256
#define HWX 65536
#define WTOT 617472

__device__ float g_bufA[2 * 64 * HWX];
__device__ float g_bufB[2 * 64 * HWX];
__device__ float g_raw[2 * 216 * HWX];
__device__ float g_col[2 * 576 * HWX];
__device__ float g_cat[128 * HWX];
__device__ __nv_bfloat16 g_wbf[2 * WTOT];   // hi plane, then lo plane

// ---------------- helpers ----------------
__device__ __forceinline__ uint32_t smem_u32(const void* p) {
    return (uint32_t)__cvta_generic_to_shared(p);
}
__device__ __forceinline__ void ldsm4(uint32_t& r0, uint32_t& r1, uint32_t& r2, uint32_t& r3, uint32_t a) {
    asm volatile("ldmatrix.sync.aligned.m8n8.x4.shared.b16 {%0,%1,%2,%3}, [%4];"
                 : "=r"(r0), "=r"(r1), "=r"(r2), "=r"(r3) : "r"(a));
}
__device__ __forceinline__ void mma16816(float* d, const uint32_t* a, uint32_t b0, uint32_t b1) {
    asm volatile("mma.sync.aligned.m16n8k16.row.col.f32.bf16.bf16.f32 "
                 "{%0,%1,%2,%3}, {%4,%5,%6,%7}, {%8,%9}, {%0,%1,%2,%3};"
                 : "+f"(d[0]), "+f"(d[1]), "+f"(d[2]), "+f"(d[3])
                 : "r"(a[0]), "r"(a[1]), "r"(a[2]), "r"(a[3]), "r"(b0), "r"(b1));
}
__device__ __forceinline__ void cp16(uint32_t daddr, const void* src, int src_sz) {
    asm volatile("cp.async.cg.shared.global [%0], [%1], 16, %2;"
                 :: "r"(daddr), "l"(src), "r"(src_sz));
}
__device__ __forceinline__ void cp4(uint32_t daddr, const void* src, int src_sz) {
    asm volatile("cp.async.ca.shared.global [%0], [%1], 4, %2;"
                 :: "r"(daddr), "l"(src), "r"(src_sz));
}
__device__ __forceinline__ void cp_commit() { asm volatile("cp.async.commit_group;"); }
__device__ __forceinline__ void cp_wait1() { asm volatile("cp.async.wait_group 1;"); }
__device__ __forceinline__ void cp_wait0() { asm volatile("cp.async.wait_group 0;"); }

// ---------------- merged weight split: fp32 -> bf16 hi/lo planes ----------------
struct SplitArgs {
    const float* p[9];
    int n[9];
    int off[9];
};

__global__ __launch_bounds__(256) void split_all_k(SplitArgs a, __nv_bfloat16* __restrict__ wbf)
{
    const int seg = blockIdx.y;
    const float* w = a.p[seg];
    const int n = a.n[seg];
    const int dst = a.off[seg];
    int i = (blockIdx.x * 256 + threadIdx.x) * 4;
    if (i >= n) return;
    float4 v = *(const float4*)(w + i);
    __nv_bfloat16 h0 = __float2bfloat16(v.x), h1 = __float2bfloat16(v.y);
    __nv_bfloat16 h2 = __float2bfloat16(v.z), h3 = __float2bfloat16(v.w);
    uint2 hp, lp;
    hp.x = ((uint32_t)__bfloat16_as_ushort(h1) << 16) | __bfloat16_as_ushort(h0);
    hp.y = ((uint32_t)__bfloat16_as_ushort(h3) << 16) | __bfloat16_as_ushort(h2);
    __nv_bfloat16 g0 = __float2bfloat16(v.x - __bfloat162float(h0));
    __nv_bfloat16 g1 = __float2bfloat16(v.y - __bfloat162float(h1));
    __nv_bfloat16 g2 = __float2bfloat16(v.z - __bfloat162float(h2));
    __nv_bfloat16 g3 = __float2bfloat16(v.w - __bfloat162float(h3));
    lp.x = ((uint32_t)__bfloat16_as_ushort(g1) << 16) | __bfloat16_as_ushort(g0);
    lp.y = ((uint32_t)__bfloat16_as_ushort(g3) << 16) | __bfloat16_as_ushort(g2);
    *(uint2*)(wbf + dst + i) = hp;
    *(uint2*)(wbf + WTOT + dst + i) = lp;
}

// ---------------- HMMA implicit-GEMM 3x3 conv, cp.async pipelined ----------------
// D[128 oc][128 px] = A[oc][kg] x B[px][kg]^T,  kg = cin*9+tap, chunks of 64 kg.
// 8 warps: warp = (mwarp 0..3) x (nwarp 0..1); warp tile 32 oc x 64 px.
// A (2 bufs x hi/lo), B (hi/lo), stage (2 bufs) in smem; rows stride 144 B.
// Prefetch chunk c+1 (cp.async) overlaps transpose+MMA of chunk c.
// grid: (512 = 256 rows x 2 col-halves, branches*mtiles), 256 threads.
#define A_OFF(d, t)  ((uint32_t)(((d) * 2 + (t)) * 18432))
#define B_OFF(t)     ((uint32_t)(73728 + (t) * 18432))
#define STG_OFF(d)   ((uint32_t)(110592 + (d) * 33792))
#define CONV_SMEM 178176

template <int KTOT, bool LRELU>
__global__ __launch_bounds__(256) void conv_mma_k(
    const float* __restrict__ x0, const float* __restrict__ x1,
    const __nv_bfloat16* __restrict__ wbf, int woff0, int woff1,
    const float* __restrict__ bias0, const float* __restrict__ bias1,
    float* __restrict__ y0, float* __restrict__ y1,
    int cout, int mtiles)
{
    extern __shared__ __align__(16) char sm[];
    const uint32_t sb = smem_u32(sm);

    const int tid = threadIdx.x;
    const int wid = tid >> 5, lane = tid & 31;
    const int mwarp = wid >> 1, nwarp = wid & 1;
    const int h = blockIdx.x >> 1;
    const int w0p = (blockIdx.x & 1) * 128;
    const int branch = blockIdx.y / mtiles;
    const int mtile = blockIdx.y - branch * mtiles;
    const float* x = branch ? x1 : x0;
    const float* bias = branch ? bias1 : bias0;
    float* y = branch ? y1 : y0;
    const int woff = branch ? woff1 : woff0;
    const int ocb = mtile * 128;
    const int crows = min(128, cout - ocb);

    constexpr int NCH = KTOT / 64;

    const int arow = tid >> 1, ahalf = tid & 1;
    const bool vrow = arow < crows;

    // prefetch chunk `c` into buffer d = c&1 (A weights + fp32 stage)
    auto prefetch = [&](int c) {
        const int d = c & 1;
        // A: 2 planes x 64 B per thread (16B-aligned cp16)
        {
            const char* sh = (const char*)(wbf + woff + (size_t)(ocb + arow) * KTOT + c * 64 + ahalf * 32);
            const char* sl = sh + (size_t)WTOT * 2;
            uint32_t da0 = sb + A_OFF(d, 0) + arow * 144 + ahalf * 64;
            uint32_t da1 = sb + A_OFF(d, 1) + arow * 144 + ahalf * 64;
            int sz = vrow ? 16 : 0;
#pragma unroll
            for (int j = 0; j < 4; ++j) {
                cp16(da0 + j * 16, sh + j * 16, sz);
                cp16(da1 + j * 16, sl + j * 16, sz);
            }
        }
        // stage: [px 128][kg 64] stride 66, element cp4 with zero-fill
        {
            uint32_t dbase = sb + STG_OFF(d);
#pragma unroll
            for (int j = 0; j < 8; ++j) {
                int kg = wid * 8 + j;
                int kga = c * 64 + kg;
                int cin = kga / 9, tap = kga - cin * 9;
                int ky = tap / 3, kx = tap - 3 * ky;
                int yy = h + ky - 1;
                bool rv = (unsigned)yy < IH;
                const float* src = x + (size_t)cin * HWX + yy * IW + (w0p - 1 + kx);
                int bad = (w0p == 0) ? (kx == 0 ? 0 : -1) : (kx == 2 ? 127 : -1);
#pragma unroll
                for (int i = 0; i < 4; ++i) {
                    int px = lane + 32 * i;
                    bool valid = rv && (px != bad);
                    cp4(dbase + (uint32_t)(px * 66 + kg) * 4, valid ? (src + px) : x, valid ? 4 : 0);
                }
            }
        }
        cp_commit();
    };

    float acc[2][8][4];
#pragma unroll
    for (int mi = 0; mi < 2; ++mi)
#pragma unroll
        for (int ni = 0; ni < 8; ++ni)
#pragma unroll
            for (int q = 0; q < 4; ++q) acc[mi][ni][q] = 0.f;

    // per-warp ldmatrix base offsets (lane-dependent row/k-half)
    const uint32_t lrow = lane & 15;
    const uint32_t lkoff = (lane >> 4) * 16;  // bytes
    const uint32_t a_base0 = sb + (uint32_t)(mwarp * 32 + lrow) * 144 + lkoff;
    const uint32_t b_base0 = sb + (uint32_t)(nwarp * 64 + lrow) * 144 + lkoff;

    prefetch(0);

#pragma unroll 1
    for (int c = 0; c < NCH; ++c) {
        const int d = c & 1;
        if (c + 1 < NCH) { prefetch(c + 1); cp_wait1(); }
        else cp_wait0();
        __syncthreads();   // stage[d] + A[d] ready; compute(c-1) done -> B reusable

        // ---- transpose + bf16 hi/lo split -> B smem (stride 144 B) ----
        {
            const float* stg = (const float*)(sm + STG_OFF(d));
            char* bh = sm + B_OFF(0);
            char* bl = sm + B_OFF(1);
#pragma unroll
            for (int it = 0; it < 16; ++it) {
                int p = wid + 8 * it;
                float2 v = *(const float2*)(stg + p * 66 + 2 * lane);
                __nv_bfloat16 h0 = __float2bfloat16(v.x);
                __nv_bfloat16 h1 = __float2bfloat16(v.y);
                uint32_t hp = ((uint32_t)__bfloat16_as_ushort(h1) << 16) | __bfloat16_as_ushort(h0);
                __nv_bfloat16 g0 = __float2bfloat16(v.x - __bfloat162float(h0));
                __nv_bfloat16 g1 = __float2bfloat16(v.y - __bfloat162float(h1));
                uint32_t lp = ((uint32_t)__bfloat16_as_ushort(g1) << 16) | __bfloat16_as_ushort(g0);
                *(uint32_t*)(bh + p * 144 + lane * 4) = hp;
                *(uint32_t*)(bl + p * 144 + lane * 4) = lp;
            }
        }
        __syncthreads();   // B ready

        // ---- compute: 4 k-steps of 16, 3 products (AhBh + AhBl + AlBh) ----
#pragma unroll
        for (int ks = 0; ks < 4; ++ks) {
            uint32_t ah[2][4], al[2][4];
#pragma unroll
            for (int mi = 0; mi < 2; ++mi) {
                ldsm4(ah[mi][0], ah[mi][1], ah[mi][2], ah[mi][3],
                      a_base0 + A_OFF(d, 0) + mi * 16 * 144 + ks * 32);
                ldsm4(al[mi][0], al[mi][1], al[mi][2], al[mi][3],
                      a_base0 + A_OFF(d, 1) + mi * 16 * 144 + ks * 32);
            }
#pragma unroll
            for (int ni2 = 0; ni2 < 4; ++ni2) {
                uint32_t bh0, bh1, bh2, bh3, bl0, bl1, bl2, bl3;
                ldsm4(bh0, bh1, bh2, bh3, b_base0 + B_OFF(0) + ni2 * 16 * 144 + ks * 32);
                ldsm4(bl0, bl1, bl2, bl3, b_base0 + B_OFF(1) + ni2 * 16 * 144 + ks * 32);
#pragma unroll
                for (int mi = 0; mi < 2; ++mi) {
                    float* d0 = acc[mi][2 * ni2];
                    float* d1 = acc[mi][2 * ni2 + 1];
                    mma16816(d0, ah[mi], bh0, bh2);
                    mma16816(d0, ah[mi], bl0, bl2);
                    mma16816(d0, al[mi], bh0, bh2);
                    mma16816(d1, ah[mi], bh1, bh3);
                    mma16816(d1, ah[mi], bl1, bl3);
                    mma16816(d1, al[mi], bh1, bh3);
                }
            }
        }
        __syncthreads();   // compute(c) done before transpose(c+1) rewrites B
    }

    // ---- epilogue: fragments -> global, bias + lrelu ----
    const int colb = w0p + nwarp * 64 + (lane & 3) * 2;
#pragma unroll
    for (int mi = 0; mi < 2; ++mi) {
        int r0 = mwarp * 32 + mi * 16 + (lane >> 2);
#pragma unroll
        for (int half = 0; half < 2; ++half) {
            int r = r0 + half * 8;
            if (r < crows) {
                float bv = __ldg(bias + ocb + r);
                float* dst = y + (size_t)(ocb + r) * HWX + h * IW;
#pragma unroll
                for (int ni = 0; ni < 8; ++ni) {
                    float v0 = acc[mi][ni][half * 2 + 0] + bv;
                    float v1 = acc[mi][ni][half * 2 + 1] + bv;
                    if (LRELU) {
                        v0 = v0 >= 0.f ? v0 : 0.1f * v0;
                        v1 = v1 >= 0.f ? v1 : 0.1f * v1;
                    }
                    *(float2*)(dst + colb + ni * 8) = make_float2(v0, v1);
                }
            }
        }
    }
}

// ---------------- deformable sampling -> col ----------------
__global__ __launch_bounds__(256) void sample_k(
    const float* __restrict__ f0, const float* __restrict__ f1,
    const float* __restrict__ rawb,
    const float* __restrict__ fl0, const float* __restrict__ fl1,
    float* __restrict__ colb)
{
    const int br = blockIdx.y;
    const float* feat = br ? f1 : f0;
    const float* raw = rawb + (size_t)br * 216 * HWX;
    const float* flow = br ? fl1 : fl0;
    float* col = colb + (size_t)br * 576 * HWX;

    const int txl = threadIdx.x;
    const int g = threadIdx.y;
    const int p = blockIdx.x * 32 + txl;
    const int h = p >> 8;
    const int w = p & 255;

    const float fy = flow[HWX + p];
    const float fx = flow[p];

#pragma unroll 1
    for (int k = 0; k < 9; ++k) {
        const int kyv = k / 3 - 1;
        const int kxv = k % 3 - 1;
        const int ch = g * 18 + k * 2;

        float ry = raw[(size_t)ch * HWX + p];
        float rx = raw[(size_t)(ch + 1) * HWX + p];
        float rm = raw[(size_t)(144 + g * 9 + k) * HWX + p];

        float ey = __expf(2.f * ry);
        float oy = 10.f * (1.f - 2.f / (ey + 1.f));
        float ex = __expf(2.f * rx);
        float ox = 10.f * (1.f - 2.f / (ex + 1.f));
        float m = 1.f / (1.f + __expf(-rm));

        float py = (float)h + (float)kyv + oy + fy;
        float px = (float)w + (float)kxv + ox + fx;
        float y0f = floorf(py), x0f = floorf(px);
        float ly = py - y0f, lx = px - x0f;
        int y0 = (int)y0f, x0 = (int)x0f;
        int y1 = y0 + 1, x1 = x0 + 1;

        bool vy0 = (y0 >= 0) && (y0 < IH);
        bool vy1 = (y1 >= 0) && (y1 < IH);
        bool vx0 = (x0 >= 0) && (x0 < IW);
        bool vx1 = (x1 >= 0) && (x1 < IW);

        float w00 = (vy0 && vx0) ? (1.f - ly) * (1.f - lx) * m : 0.f;
        float w01 = (vy0 && vx1) ? (1.f - ly) * lx * m : 0.f;
        float w10 = (vy1 && vx0) ? ly * (1.f - lx) * m : 0.f;
        float w11 = (vy1 && vx1) ? ly * lx * m : 0.f;

        int y0c = min(max(y0, 0), IH - 1), y1c = min(max(y1, 0), IH - 1);
        int x0c = min(max(x0, 0), IW - 1), x1c = min(max(x1, 0), IW - 1);
        int i00 = y0c * IW + x0c, i01 = y0c * IW + x1c;
        int i10 = y1c * IW + x0c, i11 = y1c * IW + x1c;

        const float* xb = feat + (size_t)g * 8 * HWX;
#pragma unroll
        for (int c = 0; c < 8; ++c) {
            const float* xc = xb + (size_t)c * HWX;
            float s = w00 * __ldg(xc + i00) + w01 * __ldg(xc + i01)
                    + w10 * __ldg(xc + i10) + w11 * __ldg(xc + i11);
            col[((size_t)((g * 8 + c) * 9 + k)) * HWX + p] = s;
        }
    }
}

// ---------------- GEMM: out[64][65536] = W[64][576] @ col + b ----------------
__global__ __launch_bounds__(256, 2) void gemm_col_k(
    const float* __restrict__ colb,
    const float* __restrict__ wg0, const float* __restrict__ wg1,
    const float* __restrict__ bi0, const float* __restrict__ bi1,
    float* __restrict__ outb)
{
    extern __shared__ float smem[];
    float* s_w = smem;
    float* s_c = smem + 576 * 8;

    const int tid = threadIdx.x;
    const int pb = blockIdx.x * 2048;
    const int ocb = blockIdx.y * 8;
    const int br = blockIdx.z;
    const float* col = colb + (size_t)br * 576 * HWX;
    const float* wgt = br ? wg1 : wg0;
    const float* bias = br ? bi1 : bi0;
    float* out = outb + (size_t)br * 64 * HWX;

    for (int idx = tid; idx < 576 * 8; idx += 256) {
        int i = idx >> 3;
        int oc = idx & 7;
        s_w[idx] = wgt[(ocb + oc) * 576 + i];
    }

    const uint32_t sc_base = smem_u32(s_c);
    auto stage_chunk = [&](int chunk, int buf) {
        int i0 = chunk * 4;
        uint32_t dbase = sc_base + (uint32_t)buf * (4 * 2048 * 4);
#pragma unroll
        for (int j = 0; j < 8; ++j) {
            int flat = tid + j * 256;
            int row = flat >> 9;
            int c4 = flat & 511;
            cp16(dbase + (uint32_t)(row * 2048 + c4 * 4) * 4,
                 col + (size_t)(i0 + row) * HWX + pb + c4 * 4, 16);
        }
    };

    float acc[8][8];
#pragma unroll
    for (int oc = 0; oc < 8; ++oc)
#pragma unroll
        for (int q = 0; q < 8; ++q) acc[oc][q] = 0.f;

    stage_chunk(0, 0);
    cp_commit();

#pragma unroll 1
    for (int c = 0; c < 144; ++c) {
        if (c + 1 < 144) {
            stage_chunk(c + 1, (c + 1) & 1);
            cp_commit();
            cp_wait1();
        } else {
            cp_wait0();
        }
        __syncthreads();

        const float* sbuf = s_c + (c & 1) * (4 * 2048);
#pragma unroll
        for (int kk = 0; kk < 4; ++kk) {
            float4 a = *reinterpret_cast<const float4*>(sbuf + kk * 2048 + tid * 4);
            float4 b = *reinterpret_cast<const float4*>(sbuf + kk * 2048 + 1024 + tid * 4);
            const float* wr = &s_w[(c * 4 + kk) * 8];
#pragma unroll
            for (int oc = 0; oc < 8; ++oc) {
                float wv = wr[oc];
                acc[oc][0] = fmaf(a.x, wv, acc[oc][0]);
                acc[oc][1] = fmaf(a.y, wv, acc[oc][1]);
                acc[oc][2] = fmaf(a.z, wv, acc[oc][2]);
                acc[oc][3] = fmaf(a.w, wv, acc[oc][3]);
                acc[oc][4] = fmaf(b.x, wv, acc[oc][4]);
                acc[oc][5] = fmaf(b.y, wv, acc[oc][5]);
                acc[oc][6] = fmaf(b.z, wv, acc[oc][6]);
                acc[oc][7] = fmaf(b.w, wv, acc[oc][7]);
            }
        }
        __syncthreads();
    }

#pragma unroll
    for (int oc = 0; oc < 8; ++oc) {
        float bv = bias[ocb + oc];
        float4 o1, o2;
        o1.x = acc[oc][0] + bv; o1.y = acc[oc][1] + bv;
        o1.z = acc[oc][2] + bv; o1.w = acc[oc][3] + bv;
        o2.x = acc[oc][4] + bv; o2.y = acc[oc][5] + bv;
        o2.z = acc[oc][6] + bv; o2.w = acc[oc][7] + bv;
        *reinterpret_cast<float4*>(&out[(size_t)(ocb + oc) * HWX + pb + tid * 4]) = o1;
        *reinterpret_cast<float4*>(&out[(size_t)(ocb + oc) * HWX + pb + 1024 + tid * 4]) = o2;
    }
}

// ---------------- host side ----------------
extern "C" void kernel_launch(void* const* d_in, const int* in_sizes, int n_in,
                              void* d_out, int out_size)
{
    (void)in_sizes; (void)n_in; (void)out_size;

    float *bufA, *bufB, *raw, *colp, *cat;
    __nv_bfloat16* wbf;
    cudaGetSymbolAddress((void**)&bufA, g_bufA);
    cudaGetSymbolAddress((void**)&bufB, g_bufB);
    cudaGetSymbolAddress((void**)&raw, g_raw);
    cudaGetSymbolAddress((void**)&colp, g_col);
    cudaGetSymbolAddress((void**)&cat, g_cat);
    cudaGetSymbolAddress((void**)&wbf, g_wbf);

    const float* feat0  = (const float*)d_in[0];
    const float* feat1  = (const float*)d_in[1];
    const float* extra0 = (const float*)d_in[2];
    const float* extra1 = (const float*)d_in[3];
    const float* flow0  = (const float*)d_in[4];
    const float* flow1  = (const float*)d_in[5];

    const size_t OFF64 = (size_t)64 * HWX;

    const float* Bb[2][4];
    for (int br = 0; br < 2; ++br)
        for (int j = 0; j < 4; ++j)
            Bb[br][j] = (const float*)d_in[6 + br * 8 + j * 2 + 1];
    const float* dw1 = (const float*)d_in[22];
    const float* db1 = (const float*)d_in[23];
    const float* dw2 = (const float*)d_in[24];
    const float* db2 = (const float*)d_in[25];
    const float* fb  = (const float*)d_in[27];

    const int SM_GEMM = (576 * 8 + 2 * 4 * 2048) * 4;
    cudaFuncSetAttribute(conv_mma_k<1152, true>,  cudaFuncAttributeMaxDynamicSharedMemorySize, CONV_SMEM);
    cudaFuncSetAttribute(conv_mma_k<576, true>,   cudaFuncAttributeMaxDynamicSharedMemorySize, CONV_SMEM);
    cudaFuncSetAttribute(conv_mma_k<576, false>,  cudaFuncAttributeMaxDynamicSharedMemorySize, CONV_SMEM);
    cudaFuncSetAttribute(conv_mma_k<1152, false>, cudaFuncAttributeMaxDynamicSharedMemorySize, CONV_SMEM);
    cudaFuncSetAttribute(gemm_col_k,              cudaFuncAttributeMaxDynamicSharedMemorySize, SM_GEMM);

    // weight split prologue (single launch): {input index, elems, dst offset}
    const int L[9][3] = {
        {6, 73728, 0},       {8, 36864, 73728},   {10, 36864, 110592}, {12, 124416, 147456},
        {14, 73728, 271872}, {16, 36864, 345600}, {18, 36864, 382464}, {20, 124416, 419328},
        {26, 73728, 543744}};
    SplitArgs sa;
    for (int i = 0; i < 9; ++i) {
        sa.p[i] = (const float*)d_in[L[i][0]];
        sa.n[i] = L[i][1];
        sa.off[i] = L[i][2];
    }
    split_all_k<<<dim3(122, 9), 256>>>(sa, wbf);

    conv_mma_k<1152, true><<<dim3(512, 2), 256, CONV_SMEM>>>(
        extra0, extra1, wbf, 0, 271872, Bb[0][0], Bb[1][0], bufA, bufA + OFF64, 64, 1);
    conv_mma_k<576, true><<<dim3(512, 2), 256, CONV_SMEM>>>(
        bufA, bufA + OFF64, wbf, 73728, 345600, Bb[0][1], Bb[1][1], bufB, bufB + OFF64, 64, 1);
    conv_mma_k<576, true><<<dim3(512, 2), 256, CONV_SMEM>>>(
        bufB, bufB + OFF64, wbf, 110592, 382464, Bb[0][2], Bb[1][2], bufA, bufA + OFF64, 64, 1);
    conv_mma_k<576, false><<<dim3(512, 4), 256, CONV_SMEM>>>(
        bufA, bufA + OFF64, wbf, 147456, 419328, Bb[0][3], Bb[1][3],
        raw, raw + (size_t)216 * HWX, 216, 2);

    sample_k<<<dim3(2048, 2), dim3(32, 8)>>>(feat0, feat1, raw, flow0, flow1, colp);
    gemm_col_k<<<dim3(32, 8, 2), 256, SM_GEMM>>>(colp, dw1, dw2, db1, db2, cat);

    conv_mma_k<1152, false><<<dim3(512, 1), 256, CONV_SMEM>>>(
        cat, cat, wbf, 543744, 543744, fb, fb, (float*)d_out, (float*)d_out, 64, 1);
}